// round 7
// baseline (speedup 1.0000x reference)
#include <cuda_runtime.h>
#include <cuda_bf16.h>
#include <cuda_fp16.h>
#include <math.h>
#include <cstdint>

// ---------------------------------------------------------------------------
// FraudGNN: 3-layer GAT + MLP classifier + log_softmax
// GEMMs: mma.sync fp16 2-pass (A fp16, W split hi/lo fp16), fp32 accum,
// warp tile 64x32 (LDSM-minimal), fused attn-coef epilogue, fp16 features.
// ---------------------------------------------------------------------------

#define NMAX 50176
#define TMAX 451584
#define HC   512

__device__ __half g_F[(size_t)NMAX * HC];    // GEMM output features (fp16)
__device__ __half g_X[(size_t)NMAX * HC];    // GEMM input features (fp16)
__device__ __half g_Wth[512 * 512];          // W^T hi [Nc, K]
__device__ __half g_Wtl[512 * 512];          // W^T lo
__device__ float g_B[(size_t)NMAX * 128];    // layer-3 aggregate out (fp32)
__device__ float g_S[(size_t)NMAX * 4];
__device__ float g_D[(size_t)NMAX * 4];
__device__ float g_alpha[(size_t)TMAX * 4];
__device__ float g_invden[(size_t)NMAX * 4];
__device__ int   g_rowptr[NMAX + 1];
__device__ int   g_cursor[NMAX];
__device__ int   g_csrc[TMAX];
__device__ int   g_deg[NMAX];
__device__ int   g_bsum[512];
__device__ int   g_boff[512];
__device__ int   g_idx64;

// ---------------------------------------------------------------------------
__device__ __forceinline__ uint32_t smem_u32(const void* p) {
    uint32_t a;
    asm("{ .reg .u64 t; cvta.to.shared.u64 t, %1; cvt.u32.u64 %0, t; }" : "=r"(a) : "l"(p));
    return a;
}
static __device__ __forceinline__ uint32_t sw128(uint32_t off) {
    return off ^ ((off >> 3) & 0x70);
}

#define LDSM_X4(R, a) \
    asm volatile("ldmatrix.sync.aligned.m8n8.x4.shared.b16 {%0,%1,%2,%3}, [%4];" \
        : "=r"((R)[0]), "=r"((R)[1]), "=r"((R)[2]), "=r"((R)[3]) : "r"(a))

#define MMA16816(D, A, b0, b1) \
    asm volatile("mma.sync.aligned.m16n8k16.row.col.f32.f16.f16.f32 " \
        "{%0,%1,%2,%3},{%4,%5,%6,%7},{%8,%9},{%0,%1,%2,%3};" \
        : "+f"((D)[0]), "+f"((D)[1]), "+f"((D)[2]), "+f"((D)[3]) \
        : "r"((A)[0]), "r"((A)[1]), "r"((A)[2]), "r"((A)[3]), "r"(b0), "r"(b1))

#define CP_ASYNC16(so, g) \
    asm volatile("cp.async.cg.shared.global [%0], [%1], 16;" :: "r"(so), "l"(g) : "memory")
#define CP_COMMIT() asm volatile("cp.async.commit_group;" ::: "memory")
#define CP_WAIT0()  asm volatile("cp.async.wait_group 0;" ::: "memory")
#define CP_WAIT1()  asm volatile("cp.async.wait_group 1;" ::: "memory")

// ---------------------------------------------------------------------------
__global__ void probe_idx_kernel(const int* ei32) {
    __shared__ int nz;
    if (threadIdx.x == 0) nz = 0;
    __syncthreads();
    if (ei32[2 * threadIdx.x + 1] != 0) atomicAdd(&nz, 1);
    __syncthreads();
    if (threadIdx.x == 0) g_idx64 = (nz == 0) ? 1 : 0;
}
__device__ __forceinline__ int load_idx(const void* ei, long long i) {
    return g_idx64 ? (int)((const long long*)ei)[i] : ((const int*)ei)[i];
}

// ---------------------------------------------------------------------------
__global__ void init_kernel(int N) {
    int i = blockIdx.x * blockDim.x + threadIdx.x;
    if (i < N) g_deg[i] = 0;
    if (i < NMAX * 4) { g_S[i] = 0.f; g_D[i] = 0.f; }
    int n1 = (NMAX - N) * 64;
    if (i < n1) g_X[(size_t)N * 64 + i] = __float2half(0.f);
    int n2 = (NMAX - N) * 512;
    if (i < n2) g_X[(size_t)N * 512 + i] = __float2half(0.f);
}

__global__ void split_xw_kernel(const float* __restrict__ x, int nx,
                                const float* __restrict__ W, int K, int Nc) {
    int i = blockIdx.x * blockDim.x + threadIdx.x;
    if (i < nx) g_X[i] = __float2half_rn(x[i]);
    if (i < K * Nc) {
        int n = i / K, k = i - n * K;
        float v = W[(size_t)k * Nc + n];
        __half h = __float2half_rn(v);
        g_Wth[i] = h;
        g_Wtl[i] = __float2half_rn(v - __half2float(h));
    }
}
__global__ void wt_split_kernel(const float* __restrict__ W, int K, int Nc) {
    int i = blockIdx.x * blockDim.x + threadIdx.x;
    if (i >= K * Nc) return;
    int n = i / K, k = i - n * K;
    float v = W[(size_t)k * Nc + n];
    __half h = __float2half_rn(v);
    g_Wth[i] = h;
    g_Wtl[i] = __float2half_rn(v - __half2float(h));
}

// ---------------------------------------------------------------------------
// CSR construction
// ---------------------------------------------------------------------------
__global__ void count_deg_kernel(const void* ei, int E, int N) {
    int i = blockIdx.x * blockDim.x + threadIdx.x;
    int T = E + N;
    if (i >= T) return;
    int d = (i < E) ? load_idx(ei, (long long)E + i) : (i - E);
    atomicAdd(&g_deg[d], 1);
}
__global__ void scan_p1(int N) {
    __shared__ int sm[8];
    int t = threadIdx.x;
    int i = blockIdx.x * 256 + t;
    int v = (i < N) ? g_deg[i] : 0;
#pragma unroll
    for (int o = 16; o; o >>= 1) v += __shfl_xor_sync(0xffffffffu, v, o);
    if ((t & 31) == 0) sm[t >> 5] = v;
    __syncthreads();
    if (t == 0) {
        int s = 0;
#pragma unroll
        for (int w = 0; w < 8; w++) s += sm[w];
        g_bsum[blockIdx.x] = s;
    }
}
__global__ void scan_p2(int nb, int N) {
    __shared__ int s[512];
    int t = threadIdx.x;
    s[t] = (t < nb) ? g_bsum[t] : 0;
    __syncthreads();
    for (int o = 1; o < 512; o <<= 1) {
        int v = (t >= o) ? s[t - o] : 0;
        __syncthreads();
        s[t] += v;
        __syncthreads();
    }
    g_boff[t] = (t == 0) ? 0 : s[t - 1];
    if (t == 511) g_rowptr[N] = s[t];
}
__global__ void scan_p3(int N) {
    __shared__ int s[256];
    int t = threadIdx.x;
    int i = blockIdx.x * 256 + t;
    int orig = (i < N) ? g_deg[i] : 0;
    s[t] = orig;
    __syncthreads();
    for (int o = 1; o < 256; o <<= 1) {
        int v = (t >= o) ? s[t - o] : 0;
        __syncthreads();
        s[t] += v;
        __syncthreads();
    }
    if (i < N) {
        int ex = g_boff[blockIdx.x] + s[t] - orig;
        g_rowptr[i] = ex;
        g_cursor[i] = ex;
    }
}
__global__ void scatter_kernel(const void* ei, int E, int N) {
    int i = blockIdx.x * blockDim.x + threadIdx.x;
    int T = E + N;
    if (i >= T) return;
    int s, d;
    if (i < E) {
        s = load_idx(ei, i);
        d = load_idx(ei, (long long)E + i);
    } else {
        s = d = i - E;
    }
    int pos = atomicAdd(&g_cursor[d], 1);
    g_csrc[pos] = s;
}

// ---------------------------------------------------------------------------
// fp16 mma.sync GEMM, 2-pass (A·Wh + A·Wl), fp32 accumulate.
// Block tile 128x128, warp tile 64x32 (8 warps = 2m x 4n): 8 LDSM / 32 MMA
// per k16 step. K-chunk 64, 2-stage cp.async, 2 CTAs/SM.
// Fused attn-coef epilogue: atomicAdd partial <h, a_src/a_dst> into g_S/g_D.
// ---------------------------------------------------------------------------
#define TILE_B 16384
#define STAGE_B (3 * TILE_B)
#define GSMEM (2 * STAGE_B + 1024)

__global__ __launch_bounds__(256, 2) void gemm_mma_kernel(
    const __half* __restrict__ A,
    const __half* __restrict__ Bh, const __half* __restrict__ Bl,
    __half* __restrict__ C,
    const float* __restrict__ as, const float* __restrict__ ad, int Hn,
    int M, int K, int Nc)
{
    extern __shared__ char smem_raw[];
    uint32_t sb = (smem_u32(smem_raw) + 1023u) & ~1023u;
    const int t = threadIdx.x;
    const int lane = t & 31, w = t >> 5;
    const int wm = w & 1, wn = w >> 1;     // 2m x 4n
    const int bm = blockIdx.y * 128;
    const int bn = blockIdx.x * 128;
    const int S = K >> 6;

    const __half* srcs[3] = {A, Bh, Bl};
    const int rb[3] = {bm, bn, bn};

    auto issue_stage = [&](int s) {
        uint32_t base = sb + (uint32_t)(s & 1) * STAGE_B;
#pragma unroll
        for (int tile = 0; tile < 3; tile++) {
            const __half* src = srcs[tile];
            uint32_t tb = base + (uint32_t)tile * TILE_B;
#pragma unroll
            for (int j = 0; j < 4; j++) {
                int idx = t + j * 256;
                int r = idx >> 3, c16 = idx & 7;
                const void* g = src + (size_t)(rb[tile] + r) * K + s * 64 + c16 * 8;
                uint32_t so = tb + sw128((uint32_t)(r * 128 + c16 * 16));
                CP_ASYNC16(so, g);
            }
        }
        CP_COMMIT();
    };

    const uint32_t xm = (uint32_t)((lane & 7) << 4);
    const uint32_t lrow = (uint32_t)(lane & 15);
    const uint32_t lcol = (uint32_t)((lane >> 4) * 16);
    uint32_t preA[4], preBh[2], preBl[2];
#pragma unroll
    for (int i = 0; i < 4; i++) {
        uint32_t roff = (uint32_t)(wm * 64 + i * 16) + lrow;
        preA[i] = roff * 128 + lcol;
    }
#pragma unroll
    for (int j = 0; j < 2; j++) {
        uint32_t roff = (uint32_t)(wn * 32 + j * 16) + lrow;
        preBh[j] = 1 * TILE_B + roff * 128 + lcol;
        preBl[j] = 2 * TILE_B + roff * 128 + lcol;
    }

    float d[4][4][4];   // [m-frag][n8-col][regs]
#pragma unroll
    for (int i = 0; i < 4; i++)
#pragma unroll
        for (int j = 0; j < 4; j++)
#pragma unroll
            for (int q = 0; q < 4; q++) d[i][j][q] = 0.f;

    issue_stage(0);
    for (int s = 0; s < S; s++) {
        if (s + 1 < S) { issue_stage(s + 1); CP_WAIT1(); }
        else           { CP_WAIT0(); }
        __syncthreads();
        uint32_t base = sb + (uint32_t)(s & 1) * STAGE_B;
#pragma unroll
        for (int kk = 0; kk < 4; kk++) {
            uint32_t ko = (uint32_t)(kk * 32);
            uint32_t aF[4][4], bH[2][4], bL[2][4];
#pragma unroll
            for (int i = 0; i < 4; i++)
                LDSM_X4(aF[i], base + ((preA[i] + ko) ^ xm));
#pragma unroll
            for (int j = 0; j < 2; j++) {
                LDSM_X4(bH[j], base + ((preBh[j] + ko) ^ xm));
                LDSM_X4(bL[j], base + ((preBl[j] + ko) ^ xm));
            }
#pragma unroll
            for (int i = 0; i < 4; i++) {
#pragma unroll
                for (int j = 0; j < 2; j++) {
                    MMA16816(d[i][2 * j],     aF[i], bH[j][0], bH[j][2]);
                    MMA16816(d[i][2 * j + 1], aF[i], bH[j][1], bH[j][3]);
                    MMA16816(d[i][2 * j],     aF[i], bL[j][0], bL[j][2]);
                    MMA16816(d[i][2 * j + 1], aF[i], bL[j][1], bL[j][3]);
                }
            }
        }
        __syncthreads();
    }

    // ---- epilogue: store fp16 C + fused attn partial dots (fp32) ----
    const int r0 = bm + wm * 64 + (lane >> 2);
    const int c0 = bn + wn * 32 + (lane & 3) * 2;
    const int hidx = bn >> 7;
    const int cc0 = wn * 32 + (lane & 3) * 2;

    float sv[8], dv[8];
#pragma unroll
    for (int q = 0; q < 8; q++) { sv[q] = 0.f; dv[q] = 0.f; }
#pragma unroll
    for (int i = 0; i < 4; i++) {
#pragma unroll
        for (int j = 0; j < 4; j++) {
            int r = r0 + i * 16;
            int c = c0 + j * 8;
            *(__half2*)(C + (size_t)r * Nc + c) =
                __floats2half2_rn(d[i][j][0], d[i][j][1]);
            *(__half2*)(C + (size_t)(r + 8) * Nc + c) =
                __floats2half2_rn(d[i][j][2], d[i][j][3]);
            float a0 = as[hidx * 128 + cc0 + 8 * j];
            float a1 = as[hidx * 128 + cc0 + 8 * j + 1];
            float e0 = ad[hidx * 128 + cc0 + 8 * j];
            float e1 = ad[hidx * 128 + cc0 + 8 * j + 1];
            sv[i * 2]     += d[i][j][0] * a0 + d[i][j][1] * a1;
            sv[i * 2 + 1] += d[i][j][2] * a0 + d[i][j][3] * a1;
            dv[i * 2]     += d[i][j][0] * e0 + d[i][j][1] * e1;
            dv[i * 2 + 1] += d[i][j][2] * e0 + d[i][j][3] * e1;
        }
    }
#pragma unroll
    for (int slot = 0; slot < 8; slot++) {
        int r = r0 + (slot >> 1) * 16 + (slot & 1) * 8;
        atomicAdd(&g_S[(size_t)r * Hn + hidx], sv[slot]);
        atomicAdd(&g_D[(size_t)r * Hn + hidx], dv[slot]);
    }
}

// ---------------------------------------------------------------------------
__device__ __forceinline__ float wredsum(float v) {
#pragma unroll
    for (int o = 16; o; o >>= 1) v += __shfl_xor_sync(0xffffffffu, v, o);
    return v;
}
__device__ __forceinline__ float wredmax(float v) {
#pragma unroll
    for (int o = 16; o; o >>= 1) v = fmaxf(v, __shfl_xor_sync(0xffffffffu, v, o));
    return v;
}

// ---------------------------------------------------------------------------
// per-dst segment softmax (warp per dst)
// ---------------------------------------------------------------------------
template<int H>
__global__ void edge_softmax_kernel(int N) {
    int warp = (blockIdx.x * blockDim.x + threadIdx.x) >> 5;
    int lane = threadIdx.x & 31;
    if (warp >= N) return;
    int d = warp;
    int beg = g_rowptr[d], end = g_rowptr[d + 1];

    float dl[H];
#pragma unroll
    for (int h = 0; h < H; h++) dl[h] = g_D[(size_t)d * H + h];
    float mx[H];
#pragma unroll
    for (int h = 0; h < H; h++) mx[h] = -1e30f;

    for (int p = beg + lane; p < end; p += 32) {
        int s = g_csrc[p];
#pragma unroll
        for (int h = 0; h < H; h++) {
            float e = g_S[(size_t)s * H + h] + dl[h];
            e = (e > 0.f) ? e : 0.2f * e;
            mx[h] = fmaxf(mx[h], e);
        }
    }
#pragma unroll
    for (int h = 0; h < H; h++) mx[h] = wredmax(mx[h]);

    float den[H];
#pragma unroll
    for (int h = 0; h < H; h++) den[h] = 0.f;

    for (int p = beg + lane; p < end; p += 32) {
        int s = g_csrc[p];
#pragma unroll
        for (int h = 0; h < H; h++) {
            float e = g_S[(size_t)s * H + h] + dl[h];
            e = (e > 0.f) ? e : 0.2f * e;
            float ex = __expf(e - mx[h]);
            g_alpha[(size_t)p * H + h] = ex;
            den[h] += ex;
        }
    }
#pragma unroll
    for (int h = 0; h < H; h++) den[h] = wredsum(den[h]);
    if (lane == 0) {
#pragma unroll
        for (int h = 0; h < H; h++)
            g_invden[(size_t)d * H + h] = 1.0f / den[h];
    }
}

// ---------------------------------------------------------------------------
// aggregation, HC=512 layers: 128 threads/block (1 node), edge loop unroll x2.
// ---------------------------------------------------------------------------
__global__ __launch_bounds__(128) void aggregate512_kernel(
    const __half* __restrict__ feat, const float* __restrict__ bias,
    __half* __restrict__ onext, int N)
{
    int d = blockIdx.x;
    if (d >= N) return;
    int t = threadIdx.x;
    int h = t >> 5;
    int beg = g_rowptr[d], end = g_rowptr[d + 1];
    float4 acc = make_float4(0.f, 0.f, 0.f, 0.f);
    int p = beg;
    for (; p + 2 <= end; p += 2) {
        float a0 = g_alpha[(size_t)p * 4 + h];
        float a1 = g_alpha[(size_t)(p + 1) * 4 + h];
        int s0 = g_csrc[p], s1 = g_csrc[p + 1];
        uint2 u0 = *((const uint2*)(feat + (size_t)s0 * 512) + t);
        uint2 u1 = *((const uint2*)(feat + (size_t)s1 * 512) + t);
        float2 f0 = __half22float2(*(__half2*)&u0.x);
        float2 f1 = __half22float2(*(__half2*)&u0.y);
        float2 g0 = __half22float2(*(__half2*)&u1.x);
        float2 g1 = __half22float2(*(__half2*)&u1.y);
        acc.x += a0 * f0.x + a1 * g0.x;
        acc.y += a0 * f0.y + a1 * g0.y;
        acc.z += a0 * f1.x + a1 * g1.x;
        acc.w += a0 * f1.y + a1 * g1.y;
    }
    if (p < end) {
        float a = g_alpha[(size_t)p * 4 + h];
        int s = g_csrc[p];
        uint2 u = *((const uint2*)(feat + (size_t)s * 512) + t);
        float2 f0 = __half22float2(*(__half2*)&u.x);
        float2 f1 = __half22float2(*(__half2*)&u.y);
        acc.x += a * f0.x; acc.y += a * f0.y;
        acc.z += a * f1.x; acc.w += a * f1.y;
    }
    float inv = g_invden[(size_t)d * 4 + h];
    float4 b4 = *((const float4*)bias + t);
    float v0 = fmaxf(acc.x * inv + b4.x, 0.f);
    float v1 = fmaxf(acc.y * inv + b4.y, 0.f);
    float v2 = fmaxf(acc.z * inv + b4.z, 0.f);
    float v3 = fmaxf(acc.w * inv + b4.w, 0.f);
    union { __half2 h2[2]; uint2 u; } pk;
    pk.h2[0] = __floats2half2_rn(v0, v1);
    pk.h2[1] = __floats2half2_rn(v2, v3);
    *((uint2*)(onext + (size_t)d * 512) + t) = pk.u;
    if (t < 4) {
        g_S[(size_t)d * 4 + t] = 0.f;
        g_D[(size_t)d * 4 + t] = 0.f;
    }
}

// layer-3 aggregation (H=1, C=128): one warp per node, unroll x2, fp32 out
__global__ __launch_bounds__(256) void aggregate128_kernel(
    const __half* __restrict__ feat, const float* __restrict__ bias,
    float* __restrict__ out, int N)
{
    int d = (blockIdx.x * blockDim.x + threadIdx.x) >> 5;
    if (d >= N) return;
    int lane = threadIdx.x & 31;
    int beg = g_rowptr[d], end = g_rowptr[d + 1];
    float4 acc = make_float4(0.f, 0.f, 0.f, 0.f);
    int p = beg;
    for (; p + 2 <= end; p += 2) {
        float a0 = g_alpha[p], a1 = g_alpha[p + 1];
        int s0 = g_csrc[p], s1 = g_csrc[p + 1];
        uint2 u0 = *((const uint2*)(feat + (size_t)s0 * 128) + lane);
        uint2 u1 = *((const uint2*)(feat + (size_t)s1 * 128) + lane);
        float2 f0 = __half22float2(*(__half2*)&u0.x);
        float2 f1 = __half22float2(*(__half2*)&u0.y);
        float2 g0 = __half22float2(*(__half2*)&u1.x);
        float2 g1 = __half22float2(*(__half2*)&u1.y);
        acc.x += a0 * f0.x + a1 * g0.x;
        acc.y += a0 * f0.y + a1 * g0.y;
        acc.z += a0 * f1.x + a1 * g1.x;
        acc.w += a0 * f1.y + a1 * g1.y;
    }
    if (p < end) {
        float a = g_alpha[p];
        int s = g_csrc[p];
        uint2 u = *((const uint2*)(feat + (size_t)s * 128) + lane);
        float2 f0 = __half22float2(*(__half2*)&u.x);
        float2 f1 = __half22float2(*(__half2*)&u.y);
        acc.x += a * f0.x; acc.y += a * f0.y;
        acc.z += a * f1.x; acc.w += a * f1.y;
    }
    float inv = g_invden[d];
    float4 b4 = *((const float4*)bias + lane);
    float4 v = make_float4(acc.x * inv + b4.x, acc.y * inv + b4.y,
                           acc.z * inv + b4.z, acc.w * inv + b4.w);
    *((float4*)(out + (size_t)d * 128) + lane) = v;
}

// ---------------------------------------------------------------------------
// classifier: 32 nodes per block, W1c cached in smem
// ---------------------------------------------------------------------------
__global__ __launch_bounds__(256) void classifier_kernel(
    const float* __restrict__ h3,
    const float* __restrict__ W1c, const float* __restrict__ b1c,
    const float* __restrict__ W2c, const float* __restrict__ b2c,
    float* __restrict__ out, int N)
{
    __shared__ float W1s[128][64];
    __shared__ float rows[4][128];
    __shared__ float zz[4][64];
    __shared__ float W2s[128];
    __shared__ float lgs[4][2];
    int t = threadIdx.x;
    for (int i = t; i < 128 * 64; i += 256) W1s[i >> 6][i & 63] = W1c[i];
    if (t < 128) W2s[t] = W2c[t];
    __syncthreads();
    int base = blockIdx.x * 32;
    float bb = b1c[t & 63];
    for (int it = 0; it < 8; it++) {
        int nb = base + it * 4;
#pragma unroll
        for (int j = 0; j < 2; j++) {
            int i = t + j * 256;
            int nd = i >> 7, c = i & 127;
            int node = nb + nd;
            rows[nd][c] = (node < N) ? h3[(size_t)node * 128 + c] : 0.f;
        }
        __syncthreads();
        int g = t >> 6, f = t & 63;
        float acc = bb;
#pragma unroll 16
        for (int k = 0; k < 128; k++) acc += rows[g][k] * W1s[k][f];
        zz[g][f] = fmaxf(acc, 0.f);
        __syncthreads();
        if (t < 8) {
            int gg = t >> 1, cls = t & 1;
            float a = b2c[cls];
#pragma unroll
            for (int j2 = 0; j2 < 64; j2++) a += zz[gg][j2] * W2s[j2 * 2 + cls];
            lgs[gg][cls] = a;
        }
        __syncthreads();
        if (t < 4 && nb + t < N) {
            float l0 = lgs[t][0], l1 = lgs[t][1];
            float m = fmaxf(l0, l1);
            float lse = m + logf(__expf(l0 - m) + __expf(l1 - m));
            out[(size_t)(nb + t) * 2]     = l0 - lse;
            out[(size_t)(nb + t) * 2 + 1] = l1 - lse;
        }
        __syncthreads();
    }
}

// ---------------------------------------------------------------------------
extern "C" void kernel_launch(void* const* d_in, const int* in_sizes, int n_in,
                              void* d_out, int out_size)
{
    const float* x   = (const float*)d_in[0];
    const void*  ei  = d_in[1];
    const float* W1  = (const float*)d_in[2];
    const float* as1 = (const float*)d_in[3];
    const float* ad1 = (const float*)d_in[4];
    const float* b1  = (const float*)d_in[5];
    const float* W2  = (const float*)d_in[6];
    const float* as2 = (const float*)d_in[7];
    const float* ad2 = (const float*)d_in[8];
    const float* b2  = (const float*)d_in[9];
    const float* W3  = (const float*)d_in[10];
    const float* as3 = (const float*)d_in[11];
    const float* ad3 = (const float*)d_in[12];
    const float* b3  = (const float*)d_in[13];
    const float* cW1 = (const float*)d_in[14];
    const float* cb1 = (const float*)d_in[15];
    const float* cW2 = (const float*)d_in[16];
    const float* cb2 = (const float*)d_in[17];
    float* out = (float*)d_out;

    int N = in_sizes[0] / 64;
    int E = in_sizes[1] / 2;
    int T = E + N;

    cudaFuncSetAttribute(gemm_mma_kernel, cudaFuncAttributeMaxDynamicSharedMemorySize, GSMEM);

    float *pB;
    __half *pF, *pX, *pWth, *pWtl;
    cudaGetSymbolAddress((void**)&pB, g_B);
    cudaGetSymbolAddress((void**)&pF, g_F);
    cudaGetSymbolAddress((void**)&pX, g_X);
    cudaGetSymbolAddress((void**)&pWth, g_Wth);
    cudaGetSymbolAddress((void**)&pWtl, g_Wtl);

    int mt = (N + 127) / 128;
    int nb = (N + 255) / 256;
    int swarps = (N + 7) / 8;

    // 1: probe
    probe_idx_kernel<<<1, 1024>>>((const int*)ei);
    // 2: init
    {
        int mx = NMAX * 4;
        if ((NMAX - N) * 512 > mx) mx = (NMAX - N) * 512;
        if (N > mx) mx = N;
        init_kernel<<<(mx + 255) / 256, 256>>>(N);
    }
    // 3: x->fp16 + W1 split
    split_xw_kernel<<<(N * 64 + 255) / 256, 256>>>(x, N * 64, W1, 64, 512);
    // 4: layer-1 GEMM  <-- profiled launch
    gemm_mma_kernel<<<dim3(4, mt), 256, GSMEM>>>(pX, pWth, pWtl, pF, as1, ad1, 4, N, 64, 512);
    // CSR build
    count_deg_kernel<<<(T + 255) / 256, 256>>>(ei, E, N);
    scan_p1<<<nb, 256>>>(N);
    scan_p2<<<1, 512>>>(nb, N);
    scan_p3<<<nb, 256>>>(N);
    scatter_kernel<<<(T + 255) / 256, 256>>>(ei, E, N);
    // layer 1 rest
    edge_softmax_kernel<4><<<swarps, 256>>>(N);
    aggregate512_kernel<<<N, 128>>>(pF, b1, pX, N);

    // layer 2
    wt_split_kernel<<<(512 * 512 + 255) / 256, 256>>>(W2, 512, 512);
    gemm_mma_kernel<<<dim3(4, mt), 256, GSMEM>>>(pX, pWth, pWtl, pF, as2, ad2, 4, N, 512, 512);
    edge_softmax_kernel<4><<<swarps, 256>>>(N);
    aggregate512_kernel<<<N, 128>>>(pF, b2, pX, N);

    // layer 3 (H=1, C=128)
    wt_split_kernel<<<(512 * 128 + 255) / 256, 256>>>(W3, 512, 128);
    gemm_mma_kernel<<<dim3(1, mt), 256, GSMEM>>>(pX, pWth, pWtl, pF, as3, ad3, 1, N, 512, 128);
    edge_softmax_kernel<1><<<swarps, 256>>>(N);
    aggregate128_kernel<<<(N * 32 + 255) / 256, 256>>>(pF, b3, pB, N);

    // classifier + log_softmax
    classifier_kernel<<<(N + 31) / 32, 256>>>(pB, cW1, cb1, cW2, cb2, out, N);
}

// round 8
// speedup vs baseline: 1.3129x; 1.3129x over previous
#include <cuda_runtime.h>
#include <cuda_bf16.h>
#include <cuda_fp16.h>
#include <math.h>
#include <cstdint>

// ---------------------------------------------------------------------------
// FraudGNN: 3-layer GAT + MLP classifier + log_softmax
// GEMMs: mma.sync fp16 single-pass (A fp16, W fp16), fp32 accum,
// warp tile 64x32, fused attn-coef epilogue with smem reduction (no global
// atomics), fp16 feature storage throughout.
// ---------------------------------------------------------------------------

#define NMAX 50176
#define TMAX 451584
#define HC   512

__device__ __half g_F[(size_t)NMAX * HC];    // GEMM output features (fp16)
__device__ __half g_X[(size_t)NMAX * HC];    // GEMM input features (fp16)
__device__ __half g_Wt[512 * 512];           // W^T fp16 [Nc, K]
__device__ float g_B[(size_t)NMAX * 128];    // layer-3 aggregate out (fp32)
__device__ float g_S[(size_t)NMAX * 4];
__device__ float g_D[(size_t)NMAX * 4];
__device__ float g_alpha[(size_t)TMAX * 4];
__device__ float g_invden[(size_t)NMAX * 4];
__device__ int   g_rowptr[NMAX + 1];
__device__ int   g_cursor[NMAX];
__device__ int   g_csrc[TMAX];
__device__ int   g_deg[NMAX];
__device__ int   g_bsum[512];
__device__ int   g_boff[512];
__device__ int   g_idx64;

// ---------------------------------------------------------------------------
__device__ __forceinline__ uint32_t smem_u32(const void* p) {
    uint32_t a;
    asm("{ .reg .u64 t; cvta.to.shared.u64 t, %1; cvt.u32.u64 %0, t; }" : "=r"(a) : "l"(p));
    return a;
}
static __device__ __forceinline__ uint32_t sw128(uint32_t off) {
    return off ^ ((off >> 3) & 0x70);
}

#define LDSM_X4(R, a) \
    asm volatile("ldmatrix.sync.aligned.m8n8.x4.shared.b16 {%0,%1,%2,%3}, [%4];" \
        : "=r"((R)[0]), "=r"((R)[1]), "=r"((R)[2]), "=r"((R)[3]) : "r"(a))

#define MMA16816(D, A, b0, b1) \
    asm volatile("mma.sync.aligned.m16n8k16.row.col.f32.f16.f16.f32 " \
        "{%0,%1,%2,%3},{%4,%5,%6,%7},{%8,%9},{%0,%1,%2,%3};" \
        : "+f"((D)[0]), "+f"((D)[1]), "+f"((D)[2]), "+f"((D)[3]) \
        : "r"((A)[0]), "r"((A)[1]), "r"((A)[2]), "r"((A)[3]), "r"(b0), "r"(b1))

#define CP_ASYNC16(so, g) \
    asm volatile("cp.async.cg.shared.global [%0], [%1], 16;" :: "r"(so), "l"(g) : "memory")
#define CP_COMMIT() asm volatile("cp.async.commit_group;" ::: "memory")
#define CP_WAIT0()  asm volatile("cp.async.wait_group 0;" ::: "memory")
#define CP_WAIT1()  asm volatile("cp.async.wait_group 1;" ::: "memory")

// ---------------------------------------------------------------------------
__global__ void probe_idx_kernel(const int* ei32) {
    __shared__ int nz;
    if (threadIdx.x == 0) nz = 0;
    __syncthreads();
    if (ei32[2 * threadIdx.x + 1] != 0) atomicAdd(&nz, 1);
    __syncthreads();
    if (threadIdx.x == 0) g_idx64 = (nz == 0) ? 1 : 0;
}
__device__ __forceinline__ int load_idx(const void* ei, long long i) {
    return g_idx64 ? (int)((const long long*)ei)[i] : ((const int*)ei)[i];
}

// ---------------------------------------------------------------------------
__global__ void init_kernel(int N) {
    int i = blockIdx.x * blockDim.x + threadIdx.x;
    if (i < N) g_deg[i] = 0;
    int n1 = (NMAX - N) * 64;
    if (i < n1) g_X[(size_t)N * 64 + i] = __float2half(0.f);
    int n2 = (NMAX - N) * 512;
    if (i < n2) g_X[(size_t)N * 512 + i] = __float2half(0.f);
}

__global__ void split_xw_kernel(const float* __restrict__ x, int nx,
                                const float* __restrict__ W, int K, int Nc) {
    int i = blockIdx.x * blockDim.x + threadIdx.x;
    if (i < nx) g_X[i] = __float2half_rn(x[i]);
    if (i < K * Nc) {
        int n = i / K, k = i - n * K;
        g_Wt[i] = __float2half_rn(W[(size_t)k * Nc + n]);
    }
}
__global__ void wt_kernel(const float* __restrict__ W, int K, int Nc) {
    int i = blockIdx.x * blockDim.x + threadIdx.x;
    if (i >= K * Nc) return;
    int n = i / K, k = i - n * K;
    g_Wt[i] = __float2half_rn(W[(size_t)k * Nc + n]);
}

// ---------------------------------------------------------------------------
// CSR construction
// ---------------------------------------------------------------------------
__global__ void count_deg_kernel(const void* ei, int E, int N) {
    int i = blockIdx.x * blockDim.x + threadIdx.x;
    int T = E + N;
    if (i >= T) return;
    int d = (i < E) ? load_idx(ei, (long long)E + i) : (i - E);
    atomicAdd(&g_deg[d], 1);
}
__global__ void scan_p1(int N) {
    __shared__ int sm[8];
    int t = threadIdx.x;
    int i = blockIdx.x * 256 + t;
    int v = (i < N) ? g_deg[i] : 0;
#pragma unroll
    for (int o = 16; o; o >>= 1) v += __shfl_xor_sync(0xffffffffu, v, o);
    if ((t & 31) == 0) sm[t >> 5] = v;
    __syncthreads();
    if (t == 0) {
        int s = 0;
#pragma unroll
        for (int w = 0; w < 8; w++) s += sm[w];
        g_bsum[blockIdx.x] = s;
    }
}
__global__ void scan_p2(int nb, int N) {
    __shared__ int s[512];
    int t = threadIdx.x;
    s[t] = (t < nb) ? g_bsum[t] : 0;
    __syncthreads();
    for (int o = 1; o < 512; o <<= 1) {
        int v = (t >= o) ? s[t - o] : 0;
        __syncthreads();
        s[t] += v;
        __syncthreads();
    }
    g_boff[t] = (t == 0) ? 0 : s[t - 1];
    if (t == 511) g_rowptr[N] = s[t];
}
__global__ void scan_p3(int N) {
    __shared__ int s[256];
    int t = threadIdx.x;
    int i = blockIdx.x * 256 + t;
    int orig = (i < N) ? g_deg[i] : 0;
    s[t] = orig;
    __syncthreads();
    for (int o = 1; o < 256; o <<= 1) {
        int v = (t >= o) ? s[t - o] : 0;
        __syncthreads();
        s[t] += v;
        __syncthreads();
    }
    if (i < N) {
        int ex = g_boff[blockIdx.x] + s[t] - orig;
        g_rowptr[i] = ex;
        g_cursor[i] = ex;
    }
}
__global__ void scatter_kernel(const void* ei, int E, int N) {
    int i = blockIdx.x * blockDim.x + threadIdx.x;
    int T = E + N;
    if (i >= T) return;
    int s, d;
    if (i < E) {
        s = load_idx(ei, i);
        d = load_idx(ei, (long long)E + i);
    } else {
        s = d = i - E;
    }
    int pos = atomicAdd(&g_cursor[d], 1);
    g_csrc[pos] = s;
}

// ---------------------------------------------------------------------------
// fp16 mma.sync GEMM, single-pass, fp32 accumulate.
// C[M, Nc] (fp16 out) = A[M,K] @ W^T, W stored [Nc, K] K-major.
// Block tile 128x128, warp tile 64x32 (8 warps = 2m x 4n): 6 LDSM / 16 MMA
// per warp-kstep. K-chunk 64, 2-stage cp.async, 2 CTAs/SM.
// Fused attn-coef epilogue: quad-shuffle + smem reduce + plain store
// (each (row, head) is owned by exactly one CTA: hidx == blockIdx.x).
// ---------------------------------------------------------------------------
#define TILE_B 16384
#define STAGE_B (2 * TILE_B)
#define GSMEM (2 * STAGE_B + 1024)

__global__ __launch_bounds__(256, 2) void gemm_mma_kernel(
    const __half* __restrict__ A, const __half* __restrict__ B,
    __half* __restrict__ C,
    const float* __restrict__ as, const float* __restrict__ ad, int Hn,
    int M, int K, int Nc)
{
    extern __shared__ char smem_raw[];
    __shared__ float sSD[2][128];
    uint32_t sb = (smem_u32(smem_raw) + 1023u) & ~1023u;
    const int t = threadIdx.x;
    const int lane = t & 31, w = t >> 5;
    const int wm = w & 1, wn = w >> 1;     // 2m x 4n
    const int bm = blockIdx.y * 128;
    const int bn = blockIdx.x * 128;
    const int S = K >> 6;

    if (t < 128) { sSD[0][t] = 0.f; sSD[1][t] = 0.f; }

    const __half* srcs[2] = {A, B};
    const int rb[2] = {bm, bn};

    auto issue_stage = [&](int s) {
        uint32_t base = sb + (uint32_t)(s & 1) * STAGE_B;
#pragma unroll
        for (int tile = 0; tile < 2; tile++) {
            const __half* src = srcs[tile];
            uint32_t tb = base + (uint32_t)tile * TILE_B;
#pragma unroll
            for (int j = 0; j < 4; j++) {
                int idx = t + j * 256;
                int r = idx >> 3, c16 = idx & 7;
                const void* g = src + (size_t)(rb[tile] + r) * K + s * 64 + c16 * 8;
                uint32_t so = tb + sw128((uint32_t)(r * 128 + c16 * 16));
                CP_ASYNC16(so, g);
            }
        }
        CP_COMMIT();
    };

    const uint32_t xm = (uint32_t)((lane & 7) << 4);
    const uint32_t lrow = (uint32_t)(lane & 15);
    const uint32_t lcol = (uint32_t)((lane >> 4) * 16);
    uint32_t preA[4], preB[2];
#pragma unroll
    for (int i = 0; i < 4; i++) {
        uint32_t roff = (uint32_t)(wm * 64 + i * 16) + lrow;
        preA[i] = roff * 128 + lcol;
    }
#pragma unroll
    for (int j = 0; j < 2; j++) {
        uint32_t roff = (uint32_t)(wn * 32 + j * 16) + lrow;
        preB[j] = 1 * TILE_B + roff * 128 + lcol;
    }

    float d[4][4][4];   // [m-frag][n8-col][regs]
#pragma unroll
    for (int i = 0; i < 4; i++)
#pragma unroll
        for (int j = 0; j < 4; j++)
#pragma unroll
            for (int q = 0; q < 4; q++) d[i][j][q] = 0.f;

    issue_stage(0);
    for (int s = 0; s < S; s++) {
        if (s + 1 < S) { issue_stage(s + 1); CP_WAIT1(); }
        else           { CP_WAIT0(); }
        __syncthreads();
        uint32_t base = sb + (uint32_t)(s & 1) * STAGE_B;
#pragma unroll
        for (int kk = 0; kk < 4; kk++) {
            uint32_t ko = (uint32_t)(kk * 32);
            uint32_t aF[4][4], bF[2][4];
#pragma unroll
            for (int i = 0; i < 4; i++)
                LDSM_X4(aF[i], base + ((preA[i] + ko) ^ xm));
#pragma unroll
            for (int j = 0; j < 2; j++)
                LDSM_X4(bF[j], base + ((preB[j] + ko) ^ xm));
#pragma unroll
            for (int i = 0; i < 4; i++) {
#pragma unroll
                for (int j = 0; j < 2; j++) {
                    MMA16816(d[i][2 * j],     aF[i], bF[j][0], bF[j][2]);
                    MMA16816(d[i][2 * j + 1], aF[i], bF[j][1], bF[j][3]);
                }
            }
        }
        __syncthreads();
    }

    // ---- epilogue: store fp16 C + fused attn dots (smem reduce, no atomics) -
    const int r0 = bm + wm * 64 + (lane >> 2);
    const int c0 = bn + wn * 32 + (lane & 3) * 2;
    const int hidx = bn >> 7;
    const int cc0 = wn * 32 + (lane & 3) * 2;

    float sv[8], dv[8];
#pragma unroll
    for (int q = 0; q < 8; q++) { sv[q] = 0.f; dv[q] = 0.f; }
#pragma unroll
    for (int i = 0; i < 4; i++) {
#pragma unroll
        for (int j = 0; j < 4; j++) {
            int r = r0 + i * 16;
            int c = c0 + j * 8;
            *(__half2*)(C + (size_t)r * Nc + c) =
                __floats2half2_rn(d[i][j][0], d[i][j][1]);
            *(__half2*)(C + (size_t)(r + 8) * Nc + c) =
                __floats2half2_rn(d[i][j][2], d[i][j][3]);
            float a0 = as[hidx * 128 + cc0 + 8 * j];
            float a1 = as[hidx * 128 + cc0 + 8 * j + 1];
            float e0 = ad[hidx * 128 + cc0 + 8 * j];
            float e1 = ad[hidx * 128 + cc0 + 8 * j + 1];
            sv[i * 2]     += d[i][j][0] * a0 + d[i][j][1] * a1;
            sv[i * 2 + 1] += d[i][j][2] * a0 + d[i][j][3] * a1;
            dv[i * 2]     += d[i][j][0] * e0 + d[i][j][1] * e1;
            dv[i * 2 + 1] += d[i][j][2] * e0 + d[i][j][3] * e1;
        }
    }
    // quad reduce (lanes 0-3 hold different cols of the same row)
#pragma unroll
    for (int slot = 0; slot < 8; slot++) {
        sv[slot] += __shfl_xor_sync(0xffffffffu, sv[slot], 1);
        sv[slot] += __shfl_xor_sync(0xffffffffu, sv[slot], 2);
        dv[slot] += __shfl_xor_sync(0xffffffffu, dv[slot], 1);
        dv[slot] += __shfl_xor_sync(0xffffffffu, dv[slot], 2);
    }
    if ((lane & 3) == 0) {
#pragma unroll
        for (int slot = 0; slot < 8; slot++) {
            int lr = wm * 64 + (slot >> 1) * 16 + (slot & 1) * 8 + (lane >> 2);
            atomicAdd(&sSD[0][lr], sv[slot]);
            atomicAdd(&sSD[1][lr], dv[slot]);
        }
    }
    __syncthreads();
    if (t < 128) {
        int r = bm + t;
        g_S[(size_t)r * Hn + hidx] = sSD[0][t];
        g_D[(size_t)r * Hn + hidx] = sSD[1][t];
    }
}

// ---------------------------------------------------------------------------
__device__ __forceinline__ float wredsum(float v) {
#pragma unroll
    for (int o = 16; o; o >>= 1) v += __shfl_xor_sync(0xffffffffu, v, o);
    return v;
}
__device__ __forceinline__ float wredmax(float v) {
#pragma unroll
    for (int o = 16; o; o >>= 1) v = fmaxf(v, __shfl_xor_sync(0xffffffffu, v, o));
    return v;
}

// ---------------------------------------------------------------------------
// per-dst segment softmax (warp per dst)
// ---------------------------------------------------------------------------
template<int H>
__global__ void edge_softmax_kernel(int N) {
    int warp = (blockIdx.x * blockDim.x + threadIdx.x) >> 5;
    int lane = threadIdx.x & 31;
    if (warp >= N) return;
    int d = warp;
    int beg = g_rowptr[d], end = g_rowptr[d + 1];

    float dl[H];
#pragma unroll
    for (int h = 0; h < H; h++) dl[h] = g_D[(size_t)d * H + h];
    float mx[H];
#pragma unroll
    for (int h = 0; h < H; h++) mx[h] = -1e30f;

    for (int p = beg + lane; p < end; p += 32) {
        int s = g_csrc[p];
#pragma unroll
        for (int h = 0; h < H; h++) {
            float e = g_S[(size_t)s * H + h] + dl[h];
            e = (e > 0.f) ? e : 0.2f * e;
            mx[h] = fmaxf(mx[h], e);
        }
    }
#pragma unroll
    for (int h = 0; h < H; h++) mx[h] = wredmax(mx[h]);

    float den[H];
#pragma unroll
    for (int h = 0; h < H; h++) den[h] = 0.f;

    for (int p = beg + lane; p < end; p += 32) {
        int s = g_csrc[p];
#pragma unroll
        for (int h = 0; h < H; h++) {
            float e = g_S[(size_t)s * H + h] + dl[h];
            e = (e > 0.f) ? e : 0.2f * e;
            float ex = __expf(e - mx[h]);
            g_alpha[(size_t)p * H + h] = ex;
            den[h] += ex;
        }
    }
#pragma unroll
    for (int h = 0; h < H; h++) den[h] = wredsum(den[h]);
    if (lane == 0) {
#pragma unroll
        for (int h = 0; h < H; h++)
            g_invden[(size_t)d * H + h] = 1.0f / den[h];
    }
}

// ---------------------------------------------------------------------------
// aggregation, HC=512 layers: 128 threads/block (1 node), 4 halves/thread.
// ---------------------------------------------------------------------------
__global__ __launch_bounds__(128) void aggregate512_kernel(
    const __half* __restrict__ feat, const float* __restrict__ bias,
    __half* __restrict__ onext, int N)
{
    int d = blockIdx.x;
    if (d >= N) return;
    int t = threadIdx.x;
    int h = t >> 5;
    int beg = g_rowptr[d], end = g_rowptr[d + 1];
    float4 acc = make_float4(0.f, 0.f, 0.f, 0.f);
    for (int p = beg; p < end; p++) {
        float a = g_alpha[(size_t)p * 4 + h];
        int s = g_csrc[p];
        uint2 u = *((const uint2*)(feat + (size_t)s * 512) + t);
        float2 f0 = __half22float2(*(__half2*)&u.x);
        float2 f1 = __half22float2(*(__half2*)&u.y);
        acc.x += a * f0.x; acc.y += a * f0.y;
        acc.z += a * f1.x; acc.w += a * f1.y;
    }
    float inv = g_invden[(size_t)d * 4 + h];
    float4 b4 = *((const float4*)bias + t);
    float v0 = fmaxf(acc.x * inv + b4.x, 0.f);
    float v1 = fmaxf(acc.y * inv + b4.y, 0.f);
    float v2 = fmaxf(acc.z * inv + b4.z, 0.f);
    float v3 = fmaxf(acc.w * inv + b4.w, 0.f);
    union { __half2 h2[2]; uint2 u; } pk;
    pk.h2[0] = __floats2half2_rn(v0, v1);
    pk.h2[1] = __floats2half2_rn(v2, v3);
    *((uint2*)(onext + (size_t)d * 512) + t) = pk.u;
}

// layer-3 aggregation (H=1, C=128): one warp per node, fp32 out
__global__ __launch_bounds__(256) void aggregate128_kernel(
    const __half* __restrict__ feat, const float* __restrict__ bias,
    float* __restrict__ out, int N)
{
    int d = (blockIdx.x * blockDim.x + threadIdx.x) >> 5;
    if (d >= N) return;
    int lane = threadIdx.x & 31;
    int beg = g_rowptr[d], end = g_rowptr[d + 1];
    float4 acc = make_float4(0.f, 0.f, 0.f, 0.f);
    for (int p = beg; p < end; p++) {
        float a = g_alpha[p];
        int s = g_csrc[p];
        uint2 u = *((const uint2*)(feat + (size_t)s * 128) + lane);
        float2 f0 = __half22float2(*(__half2*)&u.x);
        float2 f1 = __half22float2(*(__half2*)&u.y);
        acc.x += a * f0.x; acc.y += a * f0.y;
        acc.z += a * f1.x; acc.w += a * f1.y;
    }
    float inv = g_invden[d];
    float4 b4 = *((const float4*)bias + lane);
    float4 v = make_float4(acc.x * inv + b4.x, acc.y * inv + b4.y,
                           acc.z * inv + b4.z, acc.w * inv + b4.w);
    *((float4*)(out + (size_t)d * 128) + lane) = v;
}

// ---------------------------------------------------------------------------
// classifier: 32 nodes per block, W1c cached in smem
// ---------------------------------------------------------------------------
__global__ __launch_bounds__(256) void classifier_kernel(
    const float* __restrict__ h3,
    const float* __restrict__ W1c, const float* __restrict__ b1c,
    const float* __restrict__ W2c, const float* __restrict__ b2c,
    float* __restrict__ out, int N)
{
    __shared__ float W1s[128][64];
    __shared__ float rows[4][128];
    __shared__ float zz[4][64];
    __shared__ float W2s[128];
    __shared__ float lgs[4][2];
    int t = threadIdx.x;
    for (int i = t; i < 128 * 64; i += 256) W1s[i >> 6][i & 63] = W1c[i];
    if (t < 128) W2s[t] = W2c[t];
    __syncthreads();
    int base = blockIdx.x * 32;
    float bb = b1c[t & 63];
    for (int it = 0; it < 8; it++) {
        int nb = base + it * 4;
#pragma unroll
        for (int j = 0; j < 2; j++) {
            int i = t + j * 256;
            int nd = i >> 7, c = i & 127;
            int node = nb + nd;
            rows[nd][c] = (node < N) ? h3[(size_t)node * 128 + c] : 0.f;
        }
        __syncthreads();
        int g = t >> 6, f = t & 63;
        float acc = bb;
#pragma unroll 16
        for (int k = 0; k < 128; k++) acc += rows[g][k] * W1s[k][f];
        zz[g][f] = fmaxf(acc, 0.f);
        __syncthreads();
        if (t < 8) {
            int gg = t >> 1, cls = t & 1;
            float a = b2c[cls];
#pragma unroll
            for (int j2 = 0; j2 < 64; j2++) a += zz[gg][j2] * W2s[j2 * 2 + cls];
            lgs[gg][cls] = a;
        }
        __syncthreads();
        if (t < 4 && nb + t < N) {
            float l0 = lgs[t][0], l1 = lgs[t][1];
            float m = fmaxf(l0, l1);
            float lse = m + logf(__expf(l0 - m) + __expf(l1 - m));
            out[(size_t)(nb + t) * 2]     = l0 - lse;
            out[(size_t)(nb + t) * 2 + 1] = l1 - lse;
        }
        __syncthreads();
    }
}

// ---------------------------------------------------------------------------
extern "C" void kernel_launch(void* const* d_in, const int* in_sizes, int n_in,
                              void* d_out, int out_size)
{
    const float* x   = (const float*)d_in[0];
    const void*  ei  = d_in[1];
    const float* W1  = (const float*)d_in[2];
    const float* as1 = (const float*)d_in[3];
    const float* ad1 = (const float*)d_in[4];
    const float* b1  = (const float*)d_in[5];
    const float* W2  = (const float*)d_in[6];
    const float* as2 = (const float*)d_in[7];
    const float* ad2 = (const float*)d_in[8];
    const float* b2  = (const float*)d_in[9];
    const float* W3  = (const float*)d_in[10];
    const float* as3 = (const float*)d_in[11];
    const float* ad3 = (const float*)d_in[12];
    const float* b3  = (const float*)d_in[13];
    const float* cW1 = (const float*)d_in[14];
    const float* cb1 = (const float*)d_in[15];
    const float* cW2 = (const float*)d_in[16];
    const float* cb2 = (const float*)d_in[17];
    float* out = (float*)d_out;

    int N = in_sizes[0] / 64;
    int E = in_sizes[1] / 2;
    int T = E + N;

    cudaFuncSetAttribute(gemm_mma_kernel, cudaFuncAttributeMaxDynamicSharedMemorySize, GSMEM);

    float *pB;
    __half *pF, *pX, *pWt;
    cudaGetSymbolAddress((void**)&pB, g_B);
    cudaGetSymbolAddress((void**)&pF, g_F);
    cudaGetSymbolAddress((void**)&pX, g_X);
    cudaGetSymbolAddress((void**)&pWt, g_Wt);

    int mt = (N + 127) / 128;
    int nb = (N + 255) / 256;
    int swarps = (N + 7) / 8;

    // 1: probe
    probe_idx_kernel<<<1, 1024>>>((const int*)ei);
    // 2: init
    {
        int mx = (NMAX - N) * 512;
        if (N > mx) mx = N;
        init_kernel<<<(mx + 255) / 256, 256>>>(N);
    }
    // 3: x->fp16 + W1
    split_xw_kernel<<<(N * 64 + 255) / 256, 256>>>(x, N * 64, W1, 64, 512);
    // 4: layer-1 GEMM  <-- profiled launch
    gemm_mma_kernel<<<dim3(4, mt), 256, GSMEM>>>(pX, pWt, pF, as1, ad1, 4, N, 64, 512);
    // CSR build
    count_deg_kernel<<<(T + 255) / 256, 256>>>(ei, E, N);
    scan_p1<<<nb, 256>>>(N);
    scan_p2<<<1, 512>>>(nb, N);
    scan_p3<<<nb, 256>>>(N);
    scatter_kernel<<<(T + 255) / 256, 256>>>(ei, E, N);
    // layer 1 rest
    edge_softmax_kernel<4><<<swarps, 256>>>(N);
    aggregate512_kernel<<<N, 128>>>(pF, b1, pX, N);

    // layer 2
    wt_kernel<<<(512 * 512 + 255) / 256, 256>>>(W2, 512, 512);
    gemm_mma_kernel<<<dim3(4, mt), 256, GSMEM>>>(pX, pWt, pF, as2, ad2, 4, N, 512, 512);
    edge_softmax_kernel<4><<<swarps, 256>>>(N);
    aggregate512_kernel<<<N, 128>>>(pF, b2, pX, N);

    // layer 3 (H=1, C=128)
    wt_kernel<<<(512 * 128 + 255) / 256, 256>>>(W3, 512, 128);
    gemm_mma_kernel<<<dim3(1, mt), 256, GSMEM>>>(pX, pWt, pF, as3, ad3, 1, N, 512, 128);
    edge_softmax_kernel<1><<<swarps, 256>>>(N);
    aggregate128_kernel<<<(N * 32 + 255) / 256, 256>>>(pF, b3, pB, N);

    // classifier + log_softmax
    classifier_kernel<<<(N + 31) / 32, 256>>>(pB, cW1, cb1, cW2, cb2, out, N);
}